// round 12
// baseline (speedup 1.0000x reference)
#include <cuda_runtime.h>
#include <cuda_fp16.h>
#include <cstdint>
#include <cstddef>

#define NEXP 8
#define HID 1024
#define NTOK 8192

#define TILE_M 128
#define TILE_N 256
#define KC 32
#define NKC (HID / KC)              // 32 k-chunks
#define STAGES 4
#define NTHREADS 512

#define A_STRIDE_H 40               // halves per A row (32 + 8 pad) = 80 B
#define B_STRIDE_H 264              // halves per B k-row (256 + 8 pad) = 528 B
#define A_BYTES_H (TILE_M * A_STRIDE_H * 2)   // 10240
#define B_BYTES_H (KC * B_STRIDE_H * 2)       // 16896
#define STAGE_BYTES (A_BYTES_H + B_BYTES_H)   // 27136
#define SMEM_DYN (STAGES * STAGE_BYTES)       // 108544

#define PERM_STRIDE 1536
#define MAX_MT (PERM_STRIDE / TILE_M)   // 12
#define N_TILES (HID / TILE_N)          // 4
#define GEMM_BLOCKS (N_TILES * MAX_MT * NEXP)   // 384

#define CVT_X_BLOCKS 4096
#define CVT_W_BLOCKS 4096
#define ROUTE_BLOCKS (NTOK / 256)       // 32

// -------- device scratch (static globals: allocation-free) --------
__device__ int    g_counts[NEXP];            // zero at entry; k_gemm tail re-zeros
__device__ int    g_done;                    // zero-init; k_gemm tail re-zeros
__device__ int    g_perm[NEXP * PERM_STRIDE];
__device__ float  g_prob[NTOK];
__device__ __half g_Xh[NTOK * HID];          // 16 MB fp16 input
__device__ __half g_Wh[NEXP * HID * HID];    // 16 MB fp16 weights

// -------- helpers --------
__device__ __forceinline__ uint32_t smem_u32(const void* p) {
    uint32_t a;
    asm("{ .reg .u64 t; cvta.to.shared.u64 t, %1; cvt.u32.u64 %0, t; }"
        : "=r"(a) : "l"(p));
    return a;
}

__device__ __forceinline__ uint32_t pack_h2(float x, float y) {
    uint32_t r;
    asm("cvt.rn.f16x2.f32 %0, %1, %2;" : "=r"(r) : "f"(y), "f"(x));
    return r;
}

__device__ __forceinline__ void cp_async16(uint32_t dst, const void* src) {
    asm volatile("cp.async.cg.shared.global [%0], [%1], 16;"
                 :: "r"(dst), "l"(src) : "memory");
}
__device__ __forceinline__ void cp_commit() {
    asm volatile("cp.async.commit_group;" ::: "memory");
}
template <int N>
__device__ __forceinline__ void cp_wait() {
    asm volatile("cp.async.wait_group %0;" :: "n"(N) : "memory");
}

#define LDSM_X4(r, addr) \
    asm volatile("ldmatrix.sync.aligned.m8n8.x4.shared.b16 " \
                 "{%0,%1,%2,%3}, [%4];" \
                 : "=r"((r)[0]), "=r"((r)[1]), "=r"((r)[2]), "=r"((r)[3]) \
                 : "r"(addr))

#define LDSM_X4_T(r, addr) \
    asm volatile("ldmatrix.sync.aligned.m8n8.x4.trans.shared.b16 " \
                 "{%0,%1,%2,%3}, [%4];" \
                 : "=r"((r)[0]), "=r"((r)[1]), "=r"((r)[2]), "=r"((r)[3]) \
                 : "r"(addr))

__device__ __forceinline__ void mma_f16(float* d, const uint32_t* a,
                                        const uint32_t* b) {
    asm volatile(
        "mma.sync.aligned.m16n8k16.row.col.f32.f16.f16.f32 "
        "{%0,%1,%2,%3}, {%4,%5,%6,%7}, {%8,%9}, {%0,%1,%2,%3};"
        : "+f"(d[0]), "+f"(d[1]), "+f"(d[2]), "+f"(d[3])
        : "r"(a[0]), "r"(a[1]), "r"(a[2]), "r"(a[3]),
          "r"(b[0]), "r"(b[1]));
}

// ====== fused: fp32->fp16 convert (X, W) + routing ======
__global__ void k_cvt(const float* __restrict__ X, const float* __restrict__ W,
                      const float* __restrict__ gate) {
    const int b = blockIdx.x;
    if (b < CVT_X_BLOCKS + CVT_W_BLOCKS) {
        const bool isW = b >= CVT_X_BLOCKS;
        const size_t base = ((size_t)(isW ? b - CVT_X_BLOCKS : b) * 256
                             + threadIdx.x) * 8;
        const float4* src = reinterpret_cast<const float4*>((isW ? W : X) + base);
        float4 v0 = __ldcs(src);
        float4 v1 = __ldcs(src + 1);
        uint4 o;
        o.x = pack_h2(v0.x, v0.y);
        o.y = pack_h2(v0.z, v0.w);
        o.z = pack_h2(v1.x, v1.y);
        o.w = pack_h2(v1.z, v1.w);
        *reinterpret_cast<uint4*>((isW ? g_Wh : g_Xh) + base) = o;
    } else {
        const int t = (b - CVT_X_BLOCKS - CVT_W_BLOCKS) * 256 + threadIdx.x;
        if (t >= NTOK) return;
        float g[NEXP];
#pragma unroll
        for (int e = 0; e < NEXP; e++) g[e] = gate[t * NEXP + e];
        int be = 0; float bm = g[0];
#pragma unroll
        for (int e = 1; e < NEXP; e++) if (g[e] > bm) { bm = g[e]; be = e; }
        float s = 0.f;
#pragma unroll
        for (int e = 0; e < NEXP; e++) s += expf(g[e] - bm);
        g_prob[t] = 1.0f / s;
        int slot = atomicAdd(&g_counts[be], 1);
        if (slot < PERM_STRIDE) g_perm[be * PERM_STRIDE + slot] = t;
    }
}

// ====== CTA-done hook: last GEMM CTA re-zeros the counters ======
__device__ __forceinline__ void cta_done() {
    __syncthreads();
    if (threadIdx.x == 0) {
        __threadfence();
        if (atomicAdd(&g_done, 1) == GEMM_BLOCKS - 1) {
#pragma unroll
            for (int e = 0; e < NEXP; e++) g_counts[e] = 0;
            g_done = 0;
        }
    }
}

// ============ grouped gather-GEMM (fp16 mma.sync + ldmatrix) ============
// TILE 128x256, 16 warps (2M x 8N), warp tile 64x32, 1 CTA/SM (full RF),
// 4-stage cp.async pipeline; warp-level code identical to the proven R7 loop.
__global__ void __launch_bounds__(NTHREADS, 1)
k_gemm(const float* __restrict__ bias, float* __restrict__ out)
{
    const int e  = blockIdx.z;
    const int mt = blockIdx.y;
    const int nb = blockIdx.x * TILE_N;
    int cnt = g_counts[e];
    if (cnt > PERM_STRIDE) cnt = PERM_STRIDE;
    if (mt * TILE_M >= cnt) { cta_done(); return; }
    const int valid = min(TILE_M, cnt - mt * TILE_M);

    __shared__ int   s_tok[TILE_M];
    __shared__ float s_p[TILE_M];
    __shared__ float s_bias[TILE_N];
    extern __shared__ __align__(16) char dynsm[];

    const int tid = threadIdx.x;
    const int wid = tid >> 5;
    const int lid = tid & 31;
    const int lr  = lid >> 2;          // 0..7
    const int lc  = lid & 3;           // 0..3
    const int row16 = lid & 15;        // ldmatrix row
    const int cb    = lid >> 4;        // ldmatrix col-block (0/1)
    const int wm0 = (wid >> 3) * 64;   // 2 M-warps
    const int wn0 = (wid & 7) * 32;    // 8 N-warps

    const uint32_t dyn_base = smem_u32(dynsm);

    if (tid < TILE_M) {
        int r = (tid < valid) ? tid : 0;
        int t = g_perm[e * PERM_STRIDE + mt * TILE_M + r];
        s_tok[tid] = t;
        s_p[tid]   = g_prob[t];
    }
    if (tid < TILE_N) s_bias[tid] = bias[e * HID + nb + tid];
    __syncthreads();

    const __half* __restrict__ We = g_Wh + (size_t)e * HID * HID;

    auto load_chunk = [&](int kc, int buf) {
        const int k0 = kc * KC;
        const uint32_t a_base = dyn_base + buf * STAGE_BYTES;
        const uint32_t b_base = a_base + A_BYTES_H;
        // A: 128 rows x 4 granules(16B) = 512 -> 1/thread
        {
            int row = tid >> 2, q = tid & 3;
            cp_async16(a_base + (uint32_t)(row * (A_STRIDE_H * 2) + q * 16),
                       g_Xh + (size_t)s_tok[row] * HID + k0 + q * 8);
        }
        // B: 32 k-rows x 32 granules = 1024 -> 2/thread
#pragma unroll
        for (int i = 0; i < (KC * 32) / NTHREADS; i++) {
            int idx = tid + i * NTHREADS;
            int kr = idx >> 5, q = idx & 31;
            cp_async16(b_base + (uint32_t)(kr * (B_STRIDE_H * 2) + q * 16),
                       We + (size_t)(k0 + kr) * HID + nb + q * 8);
        }
        cp_commit();
    };

    float acc[4][4][4];
#pragma unroll
    for (int mi = 0; mi < 4; mi++)
#pragma unroll
        for (int ni = 0; ni < 4; ni++)
#pragma unroll
            for (int j = 0; j < 4; j++) acc[mi][ni][j] = 0.f;

    load_chunk(0, 0);
    load_chunk(1, 1);
    load_chunk(2, 2);

    for (int kc = 0; kc < NKC; kc++) {
        cp_wait<2>();
        __syncthreads();

        if (kc + 3 < NKC) load_chunk(kc + 3, (kc + 3) & (STAGES - 1));
        else cp_commit();   // empty group keeps the wait<2> bookkeeping exact

        const uint32_t a_sm = dyn_base + (kc & (STAGES - 1)) * STAGE_BYTES;
        const uint32_t b_sm = a_sm + A_BYTES_H;
        const uint32_t a_addr0 = a_sm + (uint32_t)(((wm0 + row16) * A_STRIDE_H
                                                    + cb * 8) * 2);
        const uint32_t b_addr0 = b_sm + (uint32_t)((row16 * B_STRIDE_H
                                                    + wn0 + cb * 8) * 2);

#pragma unroll
        for (int kk = 0; kk < 2; kk++) {          // two k16 steps
            const uint32_t akk = a_addr0 + kk * 32;              // +16 halves
            const uint32_t bkk = b_addr0 + kk * 16 * (B_STRIDE_H * 2);
            uint32_t af[4][4];
#pragma unroll
            for (int mi = 0; mi < 4; mi++)
                LDSM_X4(af[mi], akk + mi * 16 * (A_STRIDE_H * 2));
            uint32_t bf[2][4];
#pragma unroll
            for (int np = 0; np < 2; np++)
                LDSM_X4_T(bf[np], bkk + np * 32);                // +16 halves
#pragma unroll
            for (int mi = 0; mi < 4; mi++)
#pragma unroll
                for (int ni = 0; ni < 4; ni++)
                    mma_f16(acc[mi][ni], af[mi], &bf[ni >> 1][(ni & 1) * 2]);
        }
    }

    // ---------------- epilogue: p * (acc + bias) ----------------
#pragma unroll
    for (int mi = 0; mi < 4; mi++) {
        const int r0 = wm0 + mi * 16 + lr;
        const int r1 = r0 + 8;
        const bool a0 = r0 < valid;
        const bool a1 = r1 < valid;
        const float p0 = s_p[r0];
        const float p1 = s_p[r1];
        float* o0 = out + (size_t)s_tok[r0] * HID + nb;
        float* o1 = out + (size_t)s_tok[r1] * HID + nb;
#pragma unroll
        for (int ni = 0; ni < 4; ni++) {
            const int n = wn0 + ni * 8 + 2 * lc;
            const float b0 = s_bias[n];
            const float b1 = s_bias[n + 1];
            if (a0) {
                float2 v;
                v.x = p0 * (acc[mi][ni][0] + b0);
                v.y = p0 * (acc[mi][ni][1] + b1);
                *reinterpret_cast<float2*>(o0 + n) = v;
            }
            if (a1) {
                float2 v;
                v.x = p1 * (acc[mi][ni][2] + b0);
                v.y = p1 * (acc[mi][ni][3] + b1);
                *reinterpret_cast<float2*>(o1 + n) = v;
            }
        }
    }

    cta_done();
}

// ================= launch =================
extern "C" void kernel_launch(void* const* d_in, const int* in_sizes, int n_in,
                              void* d_out, int out_size) {
    const float* input = (const float*)d_in[0];   // [8192, 1024]
    const float* gate  = (const float*)d_in[1];   // [8192, 8]
    const float* W     = (const float*)d_in[2];   // [8, 1024, 1024]
    const float* b     = (const float*)d_in[3];   // [8, 1024]
    float* out = (float*)d_out;                   // [8192, 1024]

    cudaFuncSetAttribute(k_gemm, cudaFuncAttributeMaxDynamicSharedMemorySize,
                         SMEM_DYN);

    k_cvt<<<CVT_X_BLOCKS + CVT_W_BLOCKS + ROUTE_BLOCKS, 256>>>(input, W, gate);
    k_gemm<<<dim3(N_TILES, MAX_MT, NEXP), NTHREADS, SMEM_DYN>>>(b, out);
}

// round 13
// speedup vs baseline: 1.1826x; 1.1826x over previous
#include <cuda_runtime.h>
#include <cuda_fp16.h>
#include <cstdint>
#include <cstddef>

#define NEXP 8
#define HID 1024
#define NTOK 8192

#define TILE_M 128
#define TILE_N 128
#define KC 32
#define NKC (HID / KC)              // 32 k-chunks
#define STAGES 4
#define NTHREADS 256

#define A_STRIDE_H 40               // halves per A row (32 + 8 pad) = 80 B
#define B_STRIDE_H 136              // halves per B k-row (128 + 8 pad) = 272 B
#define A_BYTES_H (TILE_M * A_STRIDE_H * 2)   // 10240
#define B_BYTES_H (KC * B_STRIDE_H * 2)       // 8704
#define STAGE_BYTES (A_BYTES_H + B_BYTES_H)   // 18944
#define SMEM_DYN (STAGES * STAGE_BYTES)       // 75776

#define PERM_STRIDE 1536
#define MAX_MT (PERM_STRIDE / TILE_M)   // 12
#define N_TILES (HID / TILE_N)          // 8
#define GEMM_BLOCKS (N_TILES * MAX_MT * NEXP)   // 768

// conversion geometry: 8 floats per thread (measured-best DRAM%)
#define CVT_X_BLOCKS 4096               // 4096*256*8 = 8.39M floats (X)
#define CVT_W_BLOCKS 4096               // 8.39M floats (W)
#define ROUTE_BLOCKS (NTOK / 256)       // 32

// -------- device scratch (static globals: allocation-free) --------
__device__ int    g_counts[NEXP];            // zero at entry; k_gemm tail re-zeros
__device__ int    g_done;                    // zero-init; k_gemm tail re-zeros
__device__ int    g_perm[NEXP * PERM_STRIDE];
__device__ float  g_prob[NTOK];
__device__ __half g_Xh[NTOK * HID];          // 16 MB fp16 input
__device__ __half g_Wh[NEXP * HID * HID];    // 16 MB fp16 weights

// -------- helpers --------
__device__ __forceinline__ uint32_t smem_u32(const void* p) {
    uint32_t a;
    asm("{ .reg .u64 t; cvta.to.shared.u64 t, %1; cvt.u32.u64 %0, t; }"
        : "=r"(a) : "l"(p));
    return a;
}

__device__ __forceinline__ uint32_t pack_h2(float x, float y) {
    uint32_t r;
    asm("cvt.rn.f16x2.f32 %0, %1, %2;" : "=r"(r) : "f"(y), "f"(x));
    return r;
}

__device__ __forceinline__ void cp_async16(uint32_t dst, const void* src) {
    asm volatile("cp.async.cg.shared.global [%0], [%1], 16;"
                 :: "r"(dst), "l"(src) : "memory");
}
__device__ __forceinline__ void cp_commit() {
    asm volatile("cp.async.commit_group;" ::: "memory");
}
template <int N>
__device__ __forceinline__ void cp_wait() {
    asm volatile("cp.async.wait_group %0;" :: "n"(N) : "memory");
}

#define LDSM_X4(r, addr) \
    asm volatile("ldmatrix.sync.aligned.m8n8.x4.shared.b16 " \
                 "{%0,%1,%2,%3}, [%4];" \
                 : "=r"((r)[0]), "=r"((r)[1]), "=r"((r)[2]), "=r"((r)[3]) \
                 : "r"(addr))

#define LDSM_X4_T(r, addr) \
    asm volatile("ldmatrix.sync.aligned.m8n8.x4.trans.shared.b16 " \
                 "{%0,%1,%2,%3}, [%4];" \
                 : "=r"((r)[0]), "=r"((r)[1]), "=r"((r)[2]), "=r"((r)[3]) \
                 : "r"(addr))

__device__ __forceinline__ void mma_f16(float* d, const uint32_t* a,
                                        const uint32_t* b) {
    asm volatile(
        "mma.sync.aligned.m16n8k16.row.col.f32.f16.f16.f32 "
        "{%0,%1,%2,%3}, {%4,%5,%6,%7}, {%8,%9}, {%0,%1,%2,%3};"
        : "+f"(d[0]), "+f"(d[1]), "+f"(d[2]), "+f"(d[3])
        : "r"(a[0]), "r"(a[1]), "r"(a[2]), "r"(a[3]),
          "r"(b[0]), "r"(b[1]));
}

// ====== fused: fp32->fp16 convert (X, W) + routing (counters pre-zeroed) ====
// blocks [0, 4096)       : X convert, 8 floats/thread
// blocks [4096, 8192)    : W convert, 8 floats/thread
// blocks [8192, 8192+32) : routing (256 tokens/block)
__global__ void k_cvt(const float* __restrict__ X, const float* __restrict__ W,
                      const float* __restrict__ gate) {
    const int b = blockIdx.x;
    if (b < CVT_X_BLOCKS + CVT_W_BLOCKS) {
        const bool isW = b >= CVT_X_BLOCKS;
        const size_t base = ((size_t)(isW ? b - CVT_X_BLOCKS : b) * 256
                             + threadIdx.x) * 8;
        const float4* src = reinterpret_cast<const float4*>((isW ? W : X) + base);
        float4 v0 = __ldcs(src);         // stream: read-once fp32
        float4 v1 = __ldcs(src + 1);
        uint4 o;
        o.x = pack_h2(v0.x, v0.y);
        o.y = pack_h2(v0.z, v0.w);
        o.z = pack_h2(v1.x, v1.y);
        o.w = pack_h2(v1.z, v1.w);
        *reinterpret_cast<uint4*>((isW ? g_Wh : g_Xh) + base) = o;
    } else {
        const int t = (b - CVT_X_BLOCKS - CVT_W_BLOCKS) * 256 + threadIdx.x;
        if (t >= NTOK) return;
        float g[NEXP];
#pragma unroll
        for (int e = 0; e < NEXP; e++) g[e] = gate[t * NEXP + e];
        int be = 0; float bm = g[0];
#pragma unroll
        for (int e = 1; e < NEXP; e++) if (g[e] > bm) { bm = g[e]; be = e; }
        float s = 0.f;
#pragma unroll
        for (int e = 0; e < NEXP; e++) s += expf(g[e] - bm);
        g_prob[t] = 1.0f / s;   // softmax prob of the argmax expert
        int slot = atomicAdd(&g_counts[be], 1);
        if (slot < PERM_STRIDE) g_perm[be * PERM_STRIDE + slot] = t;
    }
}

// ====== CTA-done hook: last of the 768 GEMM CTAs re-zeros the counters ======
__device__ __forceinline__ void cta_done() {
    __syncthreads();                 // all warps past their g_counts reads
    if (threadIdx.x == 0) {
        __threadfence();
        if (atomicAdd(&g_done, 1) == GEMM_BLOCKS - 1) {
#pragma unroll
            for (int e = 0; e < NEXP; e++) g_counts[e] = 0;
            g_done = 0;
        }
    }
}

// ============ grouped gather-GEMM (fp16 mma.sync + ldmatrix) ============
__global__ void __launch_bounds__(NTHREADS, 2)
k_gemm(const float* __restrict__ bias, float* __restrict__ out)
{
    const int e  = blockIdx.z;
    const int mt = blockIdx.y;
    const int nb = blockIdx.x * TILE_N;
    int cnt = g_counts[e];
    if (cnt > PERM_STRIDE) cnt = PERM_STRIDE;
    if (mt * TILE_M >= cnt) { cta_done(); return; }
    const int valid = min(TILE_M, cnt - mt * TILE_M);

    __shared__ int   s_tok[TILE_M];
    __shared__ float s_p[TILE_M];
    __shared__ float s_bias[TILE_N];
    extern __shared__ __align__(16) char dynsm[];

    const int tid = threadIdx.x;
    const int wid = tid >> 5;
    const int lid = tid & 31;
    const int lr  = lid >> 2;          // 0..7
    const int lc  = lid & 3;           // 0..3
    const int row16 = lid & 15;        // ldmatrix row
    const int cb    = lid >> 4;        // ldmatrix col-block (0/1)
    const int wm0 = (wid >> 2) * 64;   // 2 M-warps
    const int wn0 = (wid & 3) * 32;    // 4 N-warps

    const uint32_t dyn_base = smem_u32(dynsm);

    if (tid < TILE_M) {
        int r = (tid < valid) ? tid : 0;
        int t = g_perm[e * PERM_STRIDE + mt * TILE_M + r];
        s_tok[tid] = t;
        s_p[tid]   = g_prob[t];
    }
    if (tid < TILE_N) s_bias[tid] = bias[e * HID + nb + tid];
    __syncthreads();

    const __half* __restrict__ We = g_Wh + (size_t)e * HID * HID;

    auto load_chunk = [&](int kc, int buf) {
        const int k0 = kc * KC;
        const uint32_t a_base = dyn_base + buf * STAGE_BYTES;
        const uint32_t b_base = a_base + A_BYTES_H;
        // A: 128 rows x 4 granules(16B=8 halves) = 512 -> 2/thread
#pragma unroll
        for (int i = 0; i < (TILE_M * 4) / NTHREADS; i++) {
            int idx = tid + i * NTHREADS;
            int row = idx >> 2, q = idx & 3;
            cp_async16(a_base + (uint32_t)(row * (A_STRIDE_H * 2) + q * 16),
                       g_Xh + (size_t)s_tok[row] * HID + k0 + q * 8);
        }
        // B: 32 k-rows x 16 granules = 512 -> 2/thread
#pragma unroll
        for (int i = 0; i < (KC * 16) / NTHREADS; i++) {
            int idx = tid + i * NTHREADS;
            int kr = idx >> 4, q = idx & 15;
            cp_async16(b_base + (uint32_t)(kr * (B_STRIDE_H * 2) + q * 16),
                       We + (size_t)(k0 + kr) * HID + nb + q * 8);
        }
        cp_commit();
    };

    float acc[4][4][4];
#pragma unroll
    for (int mi = 0; mi < 4; mi++)
#pragma unroll
        for (int ni = 0; ni < 4; ni++)
#pragma unroll
            for (int j = 0; j < 4; j++) acc[mi][ni][j] = 0.f;

    load_chunk(0, 0);
    load_chunk(1, 1);
    load_chunk(2, 2);

    for (int kc = 0; kc < NKC; kc++) {
        cp_wait<2>();
        __syncthreads();

        if (kc + 3 < NKC) load_chunk(kc + 3, (kc + 3) & (STAGES - 1));
        else cp_commit();   // empty group keeps the wait<2> bookkeeping exact

        const uint32_t a_sm = dyn_base + (kc & (STAGES - 1)) * STAGE_BYTES;
        const uint32_t b_sm = a_sm + A_BYTES_H;
        const uint32_t a_addr0 = a_sm + (uint32_t)(((wm0 + row16) * A_STRIDE_H
                                                    + cb * 8) * 2);
        const uint32_t b_addr0 = b_sm + (uint32_t)((row16 * B_STRIDE_H
                                                    + wn0 + cb * 8) * 2);

#pragma unroll
        for (int kk = 0; kk < 2; kk++) {          // two k16 steps
            const uint32_t akk = a_addr0 + kk * 32;              // +16 halves
            const uint32_t bkk = b_addr0 + kk * 16 * (B_STRIDE_H * 2);
            uint32_t af[4][4];
#pragma unroll
            for (int mi = 0; mi < 4; mi++)
                LDSM_X4(af[mi], akk + mi * 16 * (A_STRIDE_H * 2));
            uint32_t bf[2][4];
#pragma unroll
            for (int np = 0; np < 2; np++)
                LDSM_X4_T(bf[np], bkk + np * 32);                // +16 halves
#pragma unroll
            for (int mi = 0; mi < 4; mi++)
#pragma unroll
                for (int ni = 0; ni < 4; ni++)
                    mma_f16(acc[mi][ni], af[mi], &bf[ni >> 1][(ni & 1) * 2]);
        }
    }

    // ---------------- epilogue: p * (acc + bias) ----------------
#pragma unroll
    for (int mi = 0; mi < 4; mi++) {
        const int r0 = wm0 + mi * 16 + lr;
        const int r1 = r0 + 8;
        const bool a0 = r0 < valid;
        const bool a1 = r1 < valid;
        const float p0 = s_p[r0];
        const float p1 = s_p[r1];
        float* o0 = out + (size_t)s_tok[r0] * HID + nb;
        float* o1 = out + (size_t)s_tok[r1] * HID + nb;
#pragma unroll
        for (int ni = 0; ni < 4; ni++) {
            const int n = wn0 + ni * 8 + 2 * lc;
            const float b0 = s_bias[n];
            const float b1 = s_bias[n + 1];
            if (a0) {
                float2 v;
                v.x = p0 * (acc[mi][ni][0] + b0);
                v.y = p0 * (acc[mi][ni][1] + b1);
                *reinterpret_cast<float2*>(o0 + n) = v;
            }
            if (a1) {
                float2 v;
                v.x = p1 * (acc[mi][ni][2] + b0);
                v.y = p1 * (acc[mi][ni][3] + b1);
                *reinterpret_cast<float2*>(o1 + n) = v;
            }
        }
    }

    cta_done();
}

// ================= launch =================
extern "C" void kernel_launch(void* const* d_in, const int* in_sizes, int n_in,
                              void* d_out, int out_size) {
    const float* input = (const float*)d_in[0];   // [8192, 1024]
    const float* gate  = (const float*)d_in[1];   // [8192, 8]
    const float* W     = (const float*)d_in[2];   // [8, 1024, 1024]
    const float* b     = (const float*)d_in[3];   // [8, 1024]
    float* out = (float*)d_out;                   // [8192, 1024]

    cudaFuncSetAttribute(k_gemm, cudaFuncAttributeMaxDynamicSharedMemorySize,
                         SMEM_DYN);

    // counters are zero on entry (static init on first call; k_gemm tail resets)
    k_cvt<<<CVT_X_BLOCKS + CVT_W_BLOCKS + ROUTE_BLOCKS, 256>>>(input, W, gate);
    k_gemm<<<dim3(N_TILES, MAX_MT, NEXP), NTHREADS, SMEM_DYN>>>(b, out);
}